// round 7
// baseline (speedup 1.0000x reference)
#include <cuda_runtime.h>
#include <cuda_bf16.h>
#include <math.h>
#include <stdint.h>

#define DD 1024
#define EE 8
#define BBATCH 4
#define SSEQ 4096
#define MM (BBATCH*SSEQ)

#define NPOOL 32
#define SCH (SSEQ/NPOOL)   // 128 sequence rows per pool1 block

// -------- scratch (no allocations allowed) --------
__device__ float g_part[NPOOL*BBATCH*DD];
__device__ float g_pooled[BBATCH*DD];
__device__ float g_w[EE];
__device__ float g_mw[DD*DD];
__device__ float g_mb[DD];

// ============================================================
// pooling: mean over S
// ============================================================
__global__ void pool1_kernel(const float* __restrict__ in) {
    const int chunk = blockIdx.x;
    const int b = blockIdx.y;
    const int d4 = threadIdx.x;  // 0..255
    const float4* p = reinterpret_cast<const float4*>(in)
                    + ((size_t)b*SSEQ + (size_t)chunk*SCH)*(DD/4) + d4;
    float sx=0.f, sy=0.f, sz=0.f, sw=0.f;
    #pragma unroll 4
    for (int s = 0; s < SCH; s++) {
        float4 v = p[(size_t)s*(DD/4)];
        sx += v.x; sy += v.y; sz += v.z; sw += v.w;
    }
    reinterpret_cast<float4*>(g_part)[(chunk*BBATCH + b)*(DD/4) + d4]
        = make_float4(sx, sy, sz, sw);
}

__global__ void pool2_kernel() {
    const int i = blockIdx.x*256 + threadIdx.x;  // 0..BBATCH*DD/4-1
    float sx=0.f, sy=0.f, sz=0.f, sw=0.f;
    #pragma unroll
    for (int c = 0; c < NPOOL; c++) {
        float4 v = reinterpret_cast<const float4*>(g_part)[c*(BBATCH*DD/4) + i];
        sx += v.x; sy += v.y; sz += v.z; sw += v.w;
    }
    const float inv = 1.0f / (float)SSEQ;
    reinterpret_cast<float4*>(g_pooled)[i] = make_float4(sx*inv, sy*inv, sz*inv, sw*inv);
}

// ============================================================
// router: logits -> softmax -> batch mean
// ============================================================
__global__ void router_kernel(const float* __restrict__ rw, const float* __restrict__ rb) {
    __shared__ float sprob[BBATCH][EE];
    const int warp = threadIdx.x >> 5;
    const int lane = threadIdx.x & 31;
    const int b = warp >> 3;   // 0..3
    const int e = warp & 7;    // 0..7
    float sum = 0.f;
    for (int d = lane; d < DD; d += 32)
        sum = fmaf(g_pooled[b*DD + d], rw[e*DD + d], sum);
    #pragma unroll
    for (int o = 16; o; o >>= 1) sum += __shfl_xor_sync(0xffffffffu, sum, o);
    if (lane == 0) sprob[b][e] = sum + rb[e];
    __syncthreads();
    if (threadIdx.x < BBATCH) {
        const int bb = threadIdx.x;
        float mx = sprob[bb][0];
        #pragma unroll
        for (int ee = 1; ee < EE; ee++) mx = fmaxf(mx, sprob[bb][ee]);
        float ex[EE]; float den = 0.f;
        #pragma unroll
        for (int ee = 0; ee < EE; ee++) { ex[ee] = expf(sprob[bb][ee] - mx); den += ex[ee]; }
        #pragma unroll
        for (int ee = 0; ee < EE; ee++) sprob[bb][ee] = ex[ee] / den;
    }
    __syncthreads();
    if (threadIdx.x < EE) {
        float a = 0.f;
        #pragma unroll
        for (int bb = 0; bb < BBATCH; bb++) a += sprob[bb][threadIdx.x];
        g_w[threadIdx.x] = a * (1.0f / (float)BBATCH);
    }
}

// ============================================================
// merge expert weights: g_mw = sum_e w[e]*expert_w[e], g_mb likewise
// ============================================================
__global__ void merge_kernel(const float* __restrict__ ew, const float* __restrict__ eb) {
    float w[EE];
    #pragma unroll
    for (int e = 0; e < EE; e++) w[e] = g_w[e];
    const size_t i = (size_t)blockIdx.x*256 + threadIdx.x;  // float4 index
    float sx=0.f, sy=0.f, sz=0.f, sw=0.f;
    #pragma unroll
    for (int e = 0; e < EE; e++) {
        float4 v = reinterpret_cast<const float4*>(ew)[(size_t)e*(DD*(size_t)DD/4) + i];
        sx = fmaf(w[e], v.x, sx); sy = fmaf(w[e], v.y, sy);
        sz = fmaf(w[e], v.z, sz); sw = fmaf(w[e], v.w, sw);
    }
    reinterpret_cast<float4*>(g_mw)[i] = make_float4(sx, sy, sz, sw);
    if (i < DD/4) {
        float bx=0.f, by=0.f, bz=0.f, bw=0.f;
        #pragma unroll
        for (int e = 0; e < EE; e++) {
            float4 v = reinterpret_cast<const float4*>(eb)[e*(DD/4) + i];
            bx = fmaf(w[e], v.x, bx); by = fmaf(w[e], v.y, by);
            bz = fmaf(w[e], v.z, bz); bw = fmaf(w[e], v.w, bw);
        }
        reinterpret_cast<float4*>(g_mb)[i] = make_float4(bx, by, bz, bw);
    }
}

// ============================================================
// mma.sync GEMM: C[16384,1024] = A x g_mw^T + g_mb
// bf16 hi/lo split, 3 passes: Ah*Wh + Ah*Wl + Al*Wh, fp32 acc.
// CTA tile 256x128, 8 warps of 64x64, BK=32, double-buffered smem.
// ============================================================

#define BKC 32
#define NKCH (DD/BKC)          // 32 chunks
#define PITCH 80               // bytes per 32-col bf16 row (64B data + 16B pad)
#define A_ROWS 256
#define W_ROWS 128
#define AB_BYTES (A_ROWS*PITCH)        // 20480
#define WB_BYTES (W_ROWS*PITCH)        // 10240
#define BUF_BYTES (2*AB_BYTES + 2*WB_BYTES)   // 61440
#define GEMM_SMEM (2*BUF_BYTES)               // 122880

// offsets within buffer: Ah, Al, Wh, Wl
#define OFF_AH 0
#define OFF_AL AB_BYTES
#define OFF_WH (2*AB_BYTES)
#define OFF_WL (2*AB_BYTES + WB_BYTES)

__device__ __forceinline__ void mma16816(float acc[4], const uint32_t a[4], const uint32_t b[2]) {
    asm volatile(
        "mma.sync.aligned.m16n8k16.row.col.f32.bf16.bf16.f32 "
        "{%0,%1,%2,%3}, {%4,%5,%6,%7}, {%8,%9}, {%0,%1,%2,%3};"
        : "+f"(acc[0]), "+f"(acc[1]), "+f"(acc[2]), "+f"(acc[3])
        : "r"(a[0]), "r"(a[1]), "r"(a[2]), "r"(a[3]), "r"(b[0]), "r"(b[1]));
}

// split a float4 into bf16 hi/lo packed pairs and store 8B each
__device__ __forceinline__ void cvt_store(char* hi, char* lo, int off, float4 v) {
    __nv_bfloat162 h01 = __floats2bfloat162_rn(v.x, v.y);
    __nv_bfloat162 h23 = __floats2bfloat162_rn(v.z, v.w);
    const float2 f01 = __bfloat1622float2(h01);
    const float2 f23 = __bfloat1622float2(h23);
    __nv_bfloat162 l01 = __floats2bfloat162_rn(v.x - f01.x, v.y - f01.y);
    __nv_bfloat162 l23 = __floats2bfloat162_rn(v.z - f23.x, v.w - f23.y);
    *(uint2*)(hi + off) = make_uint2(*(uint32_t*)&h01, *(uint32_t*)&h23);
    *(uint2*)(lo + off) = make_uint2(*(uint32_t*)&l01, *(uint32_t*)&l23);
}

// load A fragments for 4 m-tiles at k-offset kk from a bf16 tile (PITCH rows)
__device__ __forceinline__ void ldA(uint32_t fr[4][4], const char* As, int wm, int g, int t, int kk) {
    #pragma unroll
    for (int mt = 0; mt < 4; mt++) {
        const char* base = As + (wm*64 + mt*16)*PITCH + (kk + 2*t)*2;
        fr[mt][0] = *(const uint32_t*)(base + g*PITCH);
        fr[mt][1] = *(const uint32_t*)(base + (g+8)*PITCH);
        fr[mt][2] = *(const uint32_t*)(base + g*PITCH + 16);
        fr[mt][3] = *(const uint32_t*)(base + (g+8)*PITCH + 16);
    }
}
// load B fragments for 8 n-tiles (W stored [n][k] row-major == B col-major)
__device__ __forceinline__ void ldB(uint32_t fr[8][2], const char* Ws, int wn, int g, int t, int kk) {
    #pragma unroll
    for (int nt = 0; nt < 8; nt++) {
        const char* base = Ws + (wn*64 + nt*8 + g)*PITCH + (kk + 2*t)*2;
        fr[nt][0] = *(const uint32_t*)(base);
        fr[nt][1] = *(const uint32_t*)(base + 16);
    }
}

__global__ __launch_bounds__(256, 1)
void gemm_mma(const float* __restrict__ A, float* __restrict__ C) {
    extern __shared__ char sm[];
    const int tid = threadIdx.x;
    const int w = tid >> 5;
    const int lane = tid & 31;
    const int wm = w >> 1;          // 0..3
    const int wn = w & 1;           // 0..1
    const int g = lane >> 2;        // 0..7
    const int t = lane & 3;         // 0..3
    const int m0 = blockIdx.y << 8; // *256
    const int n0 = blockIdx.x << 7; // *128

    // loader indices
    const int lrow = tid >> 3;      // 0..31
    const int lc4  = tid & 7;       // 0..7 (float4 within 32-col row)

    const float* Abase = A    + (size_t)(m0 + lrow)*DD + lc4*4;
    const float* Wbase = g_mw + (size_t)(n0 + lrow)*DD + lc4*4;

    float4 pa[8], pw[4];

#define PREFETCH(kb) do {                                                    \
    const int ko = (kb)*BKC;                                                 \
    _Pragma("unroll")                                                        \
    for (int p = 0; p < 8; p++)                                              \
        pa[p] = *(const float4*)(Abase + (size_t)(p*32)*DD + ko);            \
    _Pragma("unroll")                                                        \
    for (int p = 0; p < 4; p++)                                              \
        pw[p] = *(const float4*)(Wbase + (size_t)(p*32)*DD + ko);            \
} while (0)

#define COMMIT(buf) do {                                                     \
    char* base = sm + (buf)*BUF_BYTES;                                       \
    _Pragma("unroll")                                                        \
    for (int p = 0; p < 8; p++)                                              \
        cvt_store(base + OFF_AH, base + OFF_AL,                              \
                  (lrow + p*32)*PITCH + lc4*8, pa[p]);                       \
    _Pragma("unroll")                                                        \
    for (int p = 0; p < 4; p++)                                              \
        cvt_store(base + OFF_WH, base + OFF_WL,                              \
                  (lrow + p*32)*PITCH + lc4*8, pw[p]);                       \
} while (0)

    float acc[4][8][4];
    #pragma unroll
    for (int mt = 0; mt < 4; mt++)
        #pragma unroll
        for (int nt = 0; nt < 8; nt++)
            #pragma unroll
            for (int c = 0; c < 4; c++) acc[mt][nt][c] = 0.f;

    PREFETCH(0);
    COMMIT(0);
    __syncthreads();

    for (int kb = 0; kb < NKCH; kb++) {
        const int cur = kb & 1;
        if (kb + 1 < NKCH) PREFETCH(kb + 1);

        const char* base = sm + cur*BUF_BYTES;
        uint32_t af[4][4], bf[8][2];
        #pragma unroll
        for (int kk = 0; kk < BKC; kk += 16) {
            // pass 1: Ah * Wh
            ldA(af, base + OFF_AH, wm, g, t, kk);
            ldB(bf, base + OFF_WH, wn, g, t, kk);
            #pragma unroll
            for (int mt = 0; mt < 4; mt++)
                #pragma unroll
                for (int nt = 0; nt < 8; nt++)
                    mma16816(acc[mt][nt], af[mt], bf[nt]);
            // pass 2: Ah * Wl
            ldB(bf, base + OFF_WL, wn, g, t, kk);
            #pragma unroll
            for (int mt = 0; mt < 4; mt++)
                #pragma unroll
                for (int nt = 0; nt < 8; nt++)
                    mma16816(acc[mt][nt], af[mt], bf[nt]);
            // pass 3: Al * Wh
            ldA(af, base + OFF_AL, wm, g, t, kk);
            ldB(bf, base + OFF_WH, wn, g, t, kk);
            #pragma unroll
            for (int mt = 0; mt < 4; mt++)
                #pragma unroll
                for (int nt = 0; nt < 8; nt++)
                    mma16816(acc[mt][nt], af[mt], bf[nt]);
        }

        if (kb + 1 < NKCH) COMMIT(cur ^ 1);
        __syncthreads();
    }

    // epilogue: add bias, store
    #pragma unroll
    for (int nt = 0; nt < 8; nt++) {
        const int col = n0 + wn*64 + nt*8 + 2*t;
        const float b0 = g_mb[col];
        const float b1 = g_mb[col + 1];
        #pragma unroll
        for (int mt = 0; mt < 4; mt++) {
            const int row0 = m0 + wm*64 + mt*16 + g;
            float2 v0 = make_float2(acc[mt][nt][0] + b0, acc[mt][nt][1] + b1);
            float2 v1 = make_float2(acc[mt][nt][2] + b0, acc[mt][nt][3] + b1);
            *(float2*)(C + (size_t)row0*DD + col)       = v0;
            *(float2*)(C + (size_t)(row0 + 8)*DD + col) = v1;
        }
    }
#undef PREFETCH
#undef COMMIT
}

// ============================================================
// launch
// ============================================================
extern "C" void kernel_launch(void* const* d_in, const int* in_sizes, int n_in,
                              void* d_out, int out_size) {
    const float* inputs   = (const float*)d_in[0];
    const float* router_w = (const float*)d_in[1];
    const float* router_b = (const float*)d_in[2];
    const float* expert_w = (const float*)d_in[3];
    const float* expert_b = (const float*)d_in[4];
    float* out = (float*)d_out;

    cudaFuncSetAttribute(gemm_mma, cudaFuncAttributeMaxDynamicSharedMemorySize, GEMM_SMEM);

    pool1_kernel<<<dim3(NPOOL, BBATCH), 256>>>(inputs);
    pool2_kernel<<<(BBATCH*DD/4)/256, 256>>>();
    router_kernel<<<1, 1024>>>(router_w, router_b);
    merge_kernel<<<(DD*DD/4)/256, 256>>>(expert_w, expert_b);
    gemm_mma<<<dim3(DD/128, MM/256), 256, GEMM_SMEM>>>(inputs, out);
}